// round 4
// baseline (speedup 1.0000x reference)
#include <cuda_runtime.h>
#include <math.h>

#define P_   128
#define T_   2048
#define D_   128
#define H_   64
#define G_   192   // 3*H
#define OUT_ 24

// Scratch (device globals: allocation-free per harness rules)
static __device__ float g_xbuf[(size_t)P_ * T_ * G_];  // [P][T][192] = 201 MB
static __device__ float g_hs  [(size_t)P_ * T_ * H_];  // [P][T][64]  = 64 MB

// ---------------------------------------------------------------------------
// Kernel 1: x_proj[p,t,j] = dot(z[p,t,:], w_ih[p,j,:]) + b_ih[p,j]
// Grid (T/64, P), 256 threads. Register tile: 8t x 6j per thread.
// smem: zs[64][128] natural; ws transposed [k][j] with stride 193 (odd pad ->
// conflict-free scalar transpose stores and conflict-free b-frag reads).
// ---------------------------------------------------------------------------
#define XPROJ_SMEM_FLOATS (64*128 + 128*193 + 192)

__global__ __launch_bounds__(256, 1)
void xproj_kernel(const float* __restrict__ z,
                  const float* __restrict__ w_ih,
                  const float* __restrict__ b_ih)
{
    extern __shared__ float sm[];
    float* zs = sm;               // [64][128]
    float* ws = sm + 64*128;      // [128][193]
    float* bi = ws + 128*193;     // [192]

    const int tid = threadIdx.x;
    const int p   = blockIdx.y;
    const int t0  = blockIdx.x * 64;

    // load z tile (coalesced float4, natural [t][k] layout)
    {
        const float4* z4  = (const float4*)(z + ((size_t)p*T_ + t0) * D_);
        float4*       zs4 = (float4*)zs;
        for (int i = tid; i < 64*32; i += 256) zs4[i] = z4[i];
    }
    // load w_ih transposed: global [j][k] -> smem [k][j], stride 193
    {
        const float* wp = w_ih + (size_t)p * G_ * D_;
        for (int i = tid; i < G_*D_; i += 256) {
            int j = i >> 7, k = i & 127;
            ws[k*193 + j] = wp[i];
        }
    }
    if (tid < G_) bi[tid] = b_ih[p*G_ + tid];
    __syncthreads();

    const int og = tid & 31;      // j = og + 32*c
    const int tg = tid >> 5;      // t = tg*8 + r

    float acc[8][6];
    #pragma unroll
    for (int r = 0; r < 8; r++)
        #pragma unroll
        for (int c = 0; c < 6; c++) acc[r][c] = 0.f;

    for (int k = 0; k < 128; k += 4) {
        float av[8][4];
        #pragma unroll
        for (int r = 0; r < 8; r++) {
            float4 v = *(const float4*)(zs + (tg*8 + r)*128 + k);
            av[r][0] = v.x; av[r][1] = v.y; av[r][2] = v.z; av[r][3] = v.w;
        }
        #pragma unroll
        for (int kk = 0; kk < 4; kk++) {
            float bv[6];
            #pragma unroll
            for (int c = 0; c < 6; c++) bv[c] = ws[(k+kk)*193 + og + c*32];
            #pragma unroll
            for (int r = 0; r < 8; r++)
                #pragma unroll
                for (int c = 0; c < 6; c++)
                    acc[r][c] = fmaf(av[r][kk], bv[c], acc[r][c]);
        }
    }

    float* xb = g_xbuf + ((size_t)p*T_ + t0) * G_;
    #pragma unroll
    for (int r = 0; r < 8; r++)
        #pragma unroll
        for (int c = 0; c < 6; c++) {
            int j = og + c*32;
            xb[(size_t)(tg*8 + r)*G_ + j] = acc[r][c] + bi[j];
        }
}

// ---------------------------------------------------------------------------
// Kernel 2: GRU recurrence. 1 CTA per part, 192 threads (one per gate output).
// w_hh row held in registers (16 x float4). h in smem; torch gate order r,z,n.
// ---------------------------------------------------------------------------
__global__ __launch_bounds__(192, 1)
void gru_kernel(const float* __restrict__ w_hh,
                const float* __restrict__ b_hh)
{
    __shared__ __align__(16) float h_sh[64];
    __shared__ float s1[192];   // xp + hp (used for r,z)
    __shared__ float s2[64];    // hp of n-gate
    __shared__ float s3[64];    // xp of n-gate

    const int j = threadIdx.x;
    const int p = blockIdx.x;

    float4 w4[16];
    {
        const float4* wp = (const float4*)(w_hh + ((size_t)p*G_ + j) * H_);
        #pragma unroll
        for (int q = 0; q < 16; q++) w4[q] = wp[q];
    }
    const float bhh = b_hh[p*G_ + j];

    if (j < 64) h_sh[j] = 0.f;
    __syncthreads();

    const size_t xbase = (size_t)p * T_ * G_ + j;
    float xp = g_xbuf[xbase];           // prefetch t=0
    float* hout = g_hs + (size_t)p * T_ * H_;

    for (int t = 0; t < T_; t++) {
        // prefetch next timestep's x (hidden behind the dot product)
        float xpn = (t + 1 < T_) ? g_xbuf[xbase + (size_t)(t+1)*G_] : 0.f;

        float a0 = 0.f, a1 = 0.f, a2 = 0.f, a3 = 0.f;
        #pragma unroll
        for (int q = 0; q < 16; q++) {
            float4 hv = *(const float4*)(h_sh + q*4);
            a0 = fmaf(w4[q].x, hv.x, a0);
            a1 = fmaf(w4[q].y, hv.y, a1);
            a2 = fmaf(w4[q].z, hv.z, a2);
            a3 = fmaf(w4[q].w, hv.w, a3);
        }
        float hp = ((a0 + a1) + (a2 + a3)) + bhh;

        s1[j] = xp + hp;
        if (j >= 128) { s2[j - 128] = hp; s3[j - 128] = xp; }
        __syncthreads();

        if (j < 64) {
            float r = 1.f / (1.f + expf(-s1[j]));
            float u = 1.f / (1.f + expf(-s1[j + 64]));
            float n = tanhf(s3[j] + r * s2[j]);
            float hv = n + u * (h_sh[j] - n);
            h_sh[j] = hv;
            hout[(size_t)t * H_ + j] = hv;
        }
        __syncthreads();
        xp = xpn;
    }
}

// ---------------------------------------------------------------------------
// Kernel 3: fused 4-layer MLP. Grid (T/64, P), 512 threads.
// All weights transposed into smem ([k][o], odd o-stride -> conflict-free).
// Activations ping-pong in smem with row stride 132 (16B-aligned float4 rows).
// ---------------------------------------------------------------------------
#define ASTRIDE 132
#define MLP_SMEM_FLOATS (64*129 + 128*65 + 64*33 + 32*25 + 128 + 64 + 32 + 24 + 2*64*ASTRIDE)

template<int I, int O, bool RELU>
__device__ __forceinline__
void mlp_layer(int tid, const float* __restrict__ ain, float* __restrict__ aout,
               const float* __restrict__ wT, const float* __restrict__ bias)
{
    const int NOG = O / 4;                 // o = og + c*NOG
    if (tid < NOG * 16) {
        const int og = tid % NOG;
        const int tg = tid / NOG;          // t = tg*4 + r
        float acc[4][4];
        #pragma unroll
        for (int r = 0; r < 4; r++)
            #pragma unroll
            for (int c = 0; c < 4; c++) acc[r][c] = 0.f;

        for (int k = 0; k < I; k += 4) {
            float av[4][4];
            #pragma unroll
            for (int r = 0; r < 4; r++) {
                float4 v = *(const float4*)(ain + (tg*4 + r)*ASTRIDE + k);
                av[r][0] = v.x; av[r][1] = v.y; av[r][2] = v.z; av[r][3] = v.w;
            }
            #pragma unroll
            for (int kk = 0; kk < 4; kk++) {
                float bv[4];
                #pragma unroll
                for (int c = 0; c < 4; c++) bv[c] = wT[(k+kk)*(O+1) + og + c*NOG];
                #pragma unroll
                for (int r = 0; r < 4; r++)
                    #pragma unroll
                    for (int c = 0; c < 4; c++)
                        acc[r][c] = fmaf(av[r][kk], bv[c], acc[r][c]);
            }
        }
        #pragma unroll
        for (int r = 0; r < 4; r++)
            #pragma unroll
            for (int c = 0; c < 4; c++) {
                int o = og + c*NOG;
                float v = acc[r][c] + bias[o];
                if (RELU) v = fmaxf(v, 0.f);
                aout[(tg*4 + r)*ASTRIDE + o] = v;
            }
    }
}

__global__ __launch_bounds__(512, 1)
void mlp_kernel(const float* __restrict__ w1, const float* __restrict__ b1,
                const float* __restrict__ w2, const float* __restrict__ b2,
                const float* __restrict__ w3, const float* __restrict__ b3,
                const float* __restrict__ w4, const float* __restrict__ b4,
                float* __restrict__ out)
{
    extern __shared__ float sm[];
    float* W1 = sm;                 // 64*129  (I=64,  O=128)
    float* W2 = W1 + 64*129;        // 128*65  (I=128, O=64)
    float* W3 = W2 + 128*65;        // 64*33   (I=64,  O=32)
    float* W4 = W3 + 64*33;         // 32*25   (I=32,  O=24)
    float* B1 = W4 + 32*25;         // 128
    float* B2 = B1 + 128;           // 64
    float* B3 = B2 + 64;            // 32
    float* B4 = B3 + 32;            // 24
    float* AA = B4 + 24;            // 64*132  (16B-aligned: offset 19736 floats)
    float* AB = AA + 64*ASTRIDE;    // 64*132

    const int tid = threadIdx.x;
    const int p   = blockIdx.y;
    const int t0  = blockIdx.x * 64;

    {   // transposed weight loads (consecutive-k stores, odd stride -> no conflicts)
        const float* wp = w1 + (size_t)p*128*64;
        for (int i = tid; i < 128*64; i += 512) { int o = i >> 6, k = i & 63;  W1[k*129 + o] = wp[i]; }
        wp = w2 + (size_t)p*64*128;
        for (int i = tid; i < 64*128; i += 512) { int o = i >> 7, k = i & 127; W2[k*65  + o] = wp[i]; }
        wp = w3 + (size_t)p*32*64;
        for (int i = tid; i < 32*64;  i += 512) { int o = i >> 6, k = i & 63;  W3[k*33  + o] = wp[i]; }
        wp = w4 + (size_t)p*24*32;
        for (int i = tid; i < 24*32;  i += 512) { int o = i >> 5, k = i & 31;  W4[k*25  + o] = wp[i]; }
    }
    if (tid < 128) B1[tid] = b1[p*128 + tid];
    if (tid < 64)  B2[tid] = b2[p*64  + tid];
    if (tid < 32)  B3[tid] = b3[p*32  + tid];
    if (tid < 24)  B4[tid] = b4[p*24  + tid];

    {   // hidden-state tile -> AA
        const float* hp = g_hs + ((size_t)p*T_ + t0) * H_;
        for (int i = tid; i < 64*64; i += 512) { int t = i >> 6, k = i & 63; AA[t*ASTRIDE + k] = hp[i]; }
    }
    __syncthreads();

    mlp_layer<64, 128, true>(tid, AA, AB, W1, B1);
    __syncthreads();
    mlp_layer<128, 64, true>(tid, AB, AA, W2, B2);
    __syncthreads();
    mlp_layer<64, 32, true>(tid, AA, AB, W3, B3);
    __syncthreads();

    // layer 4 (32 -> 24, no relu): tiny; simple dot per (t,o)
    float* op = out + ((size_t)p*T_ + t0) * OUT_;
    for (int i = tid; i < 64*OUT_; i += 512) {
        int t = i / OUT_;
        int o = i - t*OUT_;
        float acc = B4[o];
        #pragma unroll
        for (int k = 0; k < 32; k++) acc = fmaf(AB[t*ASTRIDE + k], W4[k*25 + o], acc);
        op[i] = acc;
    }
}

// ---------------------------------------------------------------------------
extern "C" void kernel_launch(void* const* d_in, const int* in_sizes, int n_in,
                              void* d_out, int out_size)
{
    const float* z    = (const float*)d_in[0];
    const float* w_ih = (const float*)d_in[1];
    const float* w_hh = (const float*)d_in[2];
    const float* b_ih = (const float*)d_in[3];
    const float* b_hh = (const float*)d_in[4];
    const float* w1   = (const float*)d_in[5];
    const float* b1   = (const float*)d_in[6];
    const float* w2   = (const float*)d_in[7];
    const float* b2   = (const float*)d_in[8];
    const float* w3   = (const float*)d_in[9];
    const float* b3   = (const float*)d_in[10];
    const float* w4   = (const float*)d_in[11];
    const float* b4   = (const float*)d_in[12];
    float* out = (float*)d_out;

    const int xproj_smem = XPROJ_SMEM_FLOATS * 4;   // 132352 B
    const int mlp_smem   = MLP_SMEM_FLOATS  * 4;    // 146528 B
    cudaFuncSetAttribute(xproj_kernel, cudaFuncAttributeMaxDynamicSharedMemorySize, xproj_smem);
    cudaFuncSetAttribute(mlp_kernel,   cudaFuncAttributeMaxDynamicSharedMemorySize, mlp_smem);

    xproj_kernel<<<dim3(T_/64, P_), 256, xproj_smem>>>(z, w_ih, b_ih);
    gru_kernel<<<P_, 192>>>(w_hh, b_hh);
    mlp_kernel<<<dim3(T_/64, P_), 512, mlp_smem>>>(w1, b1, w2, b2, w3, b3, w4, b4, out);
}

// round 6
// speedup vs baseline: 1.1123x; 1.1123x over previous
#include <cuda_runtime.h>
#include <math.h>

#define P_   128
#define T_   2048
#define D_   128
#define H_   64
#define G_   192   // 3*H
#define OUT_ 24

typedef unsigned long long u64;

// Scratch (device globals: allocation-free per harness rules)
static __device__ float g_xbuf[(size_t)P_ * T_ * G_];  // [P][T][192]
static __device__ float g_hs  [(size_t)P_ * T_ * H_];  // [P][T][64]

// ---- packed f32x2 helpers -------------------------------------------------
__device__ __forceinline__ u64 fma2(u64 a, u64 b, u64 c) {
    u64 d; asm("fma.rn.f32x2 %0, %1, %2, %3;" : "=l"(d) : "l"(a), "l"(b), "l"(c));
    return d;
}
__device__ __forceinline__ u64 pack2(float lo, float hi) {
    u64 r; asm("mov.b64 %0, {%1, %2};" : "=l"(r) : "f"(lo), "f"(hi));
    return r;
}
__device__ __forceinline__ float sum2(u64 v) {
    float lo, hi; asm("mov.b64 {%0, %1}, %2;" : "=f"(lo), "=f"(hi) : "l"(v));
    return lo + hi;
}
// fast sigmoid / tanh (ex2.approx + rcp.approx; ~1e-6 rel err, budget 1e-3)
__device__ __forceinline__ float sigf(float x) {
    return __fdividef(1.f, 1.f + __expf(-x));
}
__device__ __forceinline__ float tanhfast(float x) {
    return 2.f * __fdividef(1.f, 1.f + __expf(-2.f * x)) - 1.f;
}

// ---------------------------------------------------------------------------
// Kernel 1: x_proj[p,t,j] = dot(z[p,t,:], w_ih[p,j,:]) + b_ih[p,j]
// Grid (32, P), 512 threads. Per-thread tile 4t x 6j, k-paired f32x2 accs.
// Weights kept in NATURAL [j][k] layout, odd stride 129 -> conflict-free
// scalar b-loads; z tile [t][k] natural, 8B-aligned u64 broadcast a-loads.
// ---------------------------------------------------------------------------
#define XP_WS 129
#define XPROJ_SMEM_FLOATS (64*128 + 192*XP_WS + 192)

__global__ __launch_bounds__(512, 1)
void xproj_kernel(const float* __restrict__ z,
                  const float* __restrict__ w_ih,
                  const float* __restrict__ b_ih)
{
    extern __shared__ float sm[];
    float* zs = sm;                 // [64][128]
    float* ws = sm + 64*128;        // [192][129]
    float* bi = ws + 192*XP_WS;     // [192]

    const int tid = threadIdx.x;
    const int p   = blockIdx.y;
    const int t0  = blockIdx.x * 64;

    // z tile, coalesced float4
    {
        const float4* z4  = (const float4*)(z + ((size_t)p*T_ + t0) * D_);
        float4*       zs4 = (float4*)zs;
        for (int i = tid; i < 64*32; i += 512) zs4[i] = z4[i];
    }
    // w_ih natural layout [j][k], row stride 129 (odd -> conflict-free)
    {
        const float* wp = w_ih + (size_t)p * G_ * D_;
        for (int i = tid; i < G_*D_; i += 512) {
            int j = i >> 7, k = i & 127;
            ws[j*XP_WS + k] = wp[i];
        }
    }
    if (tid < G_) bi[tid] = b_ih[p*G_ + tid];
    __syncthreads();

    const int og = tid & 31;      // j = og + c*32
    const int tg = tid >> 5;      // t = tg*4 + r

    u64 acc[4][6];
    #pragma unroll
    for (int r = 0; r < 4; r++)
        #pragma unroll
        for (int c = 0; c < 6; c++) acc[r][c] = 0ull;

    const float* zrow = zs + tg*4*128;

    #pragma unroll 8
    for (int k = 0; k < 128; k += 2) {
        u64 av[4];
        #pragma unroll
        for (int r = 0; r < 4; r++)
            av[r] = *(const u64*)(zrow + r*128 + k);   // broadcast within warp
        #pragma unroll
        for (int c = 0; c < 6; c++) {
            const float* wr = ws + (og + c*32)*XP_WS + k;
            u64 bv = pack2(wr[0], wr[1]);
            #pragma unroll
            for (int r = 0; r < 4; r++)
                acc[r][c] = fma2(av[r], bv, acc[r][c]);
        }
    }

    float* xb = g_xbuf + ((size_t)p*T_ + t0) * G_;
    #pragma unroll
    for (int r = 0; r < 4; r++)
        #pragma unroll
        for (int c = 0; c < 6; c++) {
            int j = og + c*32;
            xb[(size_t)(tg*4 + r)*G_ + j] = sum2(acc[r][c]) + bi[j];
        }
}

// ---------------------------------------------------------------------------
// Kernel 2: GRU recurrence. 1 CTA per part, 192 threads. w_hh row in u64
// register pairs; dot product via 32 fma2/step; fast activations.
// ---------------------------------------------------------------------------
__global__ __launch_bounds__(192, 1)
void gru_kernel(const float* __restrict__ w_hh,
                const float* __restrict__ b_hh)
{
    __shared__ __align__(16) float h_sh[64];
    __shared__ float s1[192];   // xp + hp (r,z gates)
    __shared__ float s2[64];    // hp of n-gate
    __shared__ float s3[64];    // xp of n-gate

    const int j = threadIdx.x;
    const int p = blockIdx.x;

    u64 wr[32];                 // 64 weights as 32 k-pairs
    {
        const u64* wp = (const u64*)(w_hh + ((size_t)p*G_ + j) * H_);
        #pragma unroll
        for (int q = 0; q < 32; q++) wr[q] = wp[q];
    }
    const float bhh = b_hh[p*G_ + j];

    if (j < 64) h_sh[j] = 0.f;
    __syncthreads();

    const size_t xbase = (size_t)p * T_ * G_ + j;
    float xp = g_xbuf[xbase];           // prefetch t=0
    float* hout = g_hs + (size_t)p * T_ * H_;

    for (int t = 0; t < T_; t++) {
        float xpn = (t + 1 < T_) ? g_xbuf[xbase + (size_t)(t+1)*G_] : 0.f;

        u64 a0 = 0ull, a1 = 0ull, a2 = 0ull, a3 = 0ull;
        #pragma unroll
        for (int q = 0; q < 8; q++) {
            ulonglong2 h0 = *(const ulonglong2*)(h_sh + q*8);
            ulonglong2 h1 = *(const ulonglong2*)(h_sh + q*8 + 4);
            a0 = fma2(wr[q*4+0], h0.x, a0);
            a1 = fma2(wr[q*4+1], h0.y, a1);
            a2 = fma2(wr[q*4+2], h1.x, a2);
            a3 = fma2(wr[q*4+3], h1.y, a3);
        }
        float hp = (sum2(a0) + sum2(a1)) + (sum2(a2) + sum2(a3)) + bhh;

        s1[j] = xp + hp;
        if (j >= 128) { s2[j - 128] = hp; s3[j - 128] = xp; }
        __syncthreads();

        if (j < 64) {
            float r = sigf(s1[j]);
            float u = sigf(s1[j + 64]);
            float n = tanhfast(s3[j] + r * s2[j]);
            float hv = n + u * (h_sh[j] - n);
            h_sh[j] = hv;
            hout[(size_t)t * H_ + j] = hv;
        }
        __syncthreads();
        xp = xpn;
    }
}

// ---------------------------------------------------------------------------
// Kernel 3: fused 4-layer MLP. Grid (32, P), 512 threads, ALL active in
// every layer. Weights in natural [o][k] layout, odd stride -> conflict-free.
// k-paired f32x2 accumulators. Activations ping-pong, row stride 132.
// ---------------------------------------------------------------------------
#define ASTRIDE 132
#define MLP_SMEM_FLOATS (128*65 + 64*129 + 32*65 + 24*33 + 128 + 64 + 32 + 24 + 2*64*ASTRIDE)

// OGN = O/4 output-groups; TGN = 512/OGN t-groups; ROWS = 64/TGN = OGN/8.
template<int I, int O, bool RELU>
__device__ __forceinline__
void mlp_layer(int tid, const float* __restrict__ ain, float* __restrict__ aout,
               const float* __restrict__ W, const float* __restrict__ bias)
{
    constexpr int OGN  = O / 4;
    constexpr int ROWS = OGN / 8;        // 4 / 2 / 1
    constexpr int WS   = I + 1;          // odd row stride

    const int og = tid % OGN;
    const int tg = tid / OGN;            // t = tg*ROWS + r

    u64 acc[ROWS][4];
    #pragma unroll
    for (int r = 0; r < ROWS; r++)
        #pragma unroll
        for (int c = 0; c < 4; c++) acc[r][c] = 0ull;

    const float* arow = ain + tg*ROWS*ASTRIDE;

    #pragma unroll 8
    for (int k = 0; k < I; k += 2) {
        u64 av[ROWS];
        #pragma unroll
        for (int r = 0; r < ROWS; r++)
            av[r] = *(const u64*)(arow + r*ASTRIDE + k);
        #pragma unroll
        for (int c = 0; c < 4; c++) {
            const float* wrow = W + (og + c*OGN)*WS + k;
            u64 bv = pack2(wrow[0], wrow[1]);
            #pragma unroll
            for (int r = 0; r < ROWS; r++)
                acc[r][c] = fma2(av[r], bv, acc[r][c]);
        }
    }

    #pragma unroll
    for (int r = 0; r < ROWS; r++)
        #pragma unroll
        for (int c = 0; c < 4; c++) {
            int o = og + c*OGN;
            float v = sum2(acc[r][c]) + bias[o];
            if (RELU) v = fmaxf(v, 0.f);
            aout[(tg*ROWS + r)*ASTRIDE + o] = v;
        }
}

__global__ __launch_bounds__(512, 1)
void mlp_kernel(const float* __restrict__ w1, const float* __restrict__ b1,
                const float* __restrict__ w2, const float* __restrict__ b2,
                const float* __restrict__ w3, const float* __restrict__ b3,
                const float* __restrict__ w4, const float* __restrict__ b4,
                float* __restrict__ out)
{
    extern __shared__ float sm[];
    float* W1 = sm;                 // 128 x 65  (O=128, I=64)
    float* W2 = W1 + 128*65;        // 64  x 129 (O=64,  I=128)
    float* W3 = W2 + 64*129;        // 32  x 65  (O=32,  I=64)
    float* W4 = W3 + 32*65;         // 24  x 33  (O=24,  I=32)
    float* B1 = W4 + 24*33;
    float* B2 = B1 + 128;
    float* B3 = B2 + 64;
    float* B4 = B3 + 32;
    float* AA = B4 + 24;            // 64 x 132
    float* AB = AA + 64*ASTRIDE;    // 64 x 132

    const int tid = threadIdx.x;
    const int p   = blockIdx.y;
    const int t0  = blockIdx.x * 64;

    {   // natural-layout weight loads (coalesced reads, conflict-free stores)
        const float* wp = w1 + (size_t)p*128*64;
        for (int i = tid; i < 128*64; i += 512) { int o = i >> 6, k = i & 63;  W1[o*65  + k] = wp[i]; }
        wp = w2 + (size_t)p*64*128;
        for (int i = tid; i < 64*128; i += 512) { int o = i >> 7, k = i & 127; W2[o*129 + k] = wp[i]; }
        wp = w3 + (size_t)p*32*64;
        for (int i = tid; i < 32*64;  i += 512) { int o = i >> 6, k = i & 63;  W3[o*65  + k] = wp[i]; }
        wp = w4 + (size_t)p*24*32;
        for (int i = tid; i < 24*32;  i += 512) { int o = i >> 5, k = i & 31;  W4[o*33  + k] = wp[i]; }
    }
    if (tid < 128) B1[tid] = b1[p*128 + tid];
    if (tid < 64)  B2[tid] = b2[p*64  + tid];
    if (tid < 32)  B3[tid] = b3[p*32  + tid];
    if (tid < 24)  B4[tid] = b4[p*24  + tid];

    {   // hidden-state tile -> AA
        const float* hp = g_hs + ((size_t)p*T_ + t0) * H_;
        for (int i = tid; i < 64*64; i += 512) { int t = i >> 6, k = i & 63; AA[t*ASTRIDE + k] = hp[i]; }
    }
    __syncthreads();

    mlp_layer<64, 128, true>(tid, AA, AB, W1, B1);
    __syncthreads();
    mlp_layer<128, 64, true>(tid, AB, AA, W2, B2);
    __syncthreads();
    mlp_layer<64, 32, true>(tid, AA, AB, W3, B3);
    __syncthreads();

    // layer 4 (32 -> 24, no relu): tiny; f32x2 dot per (t,o)
    float* op = out + ((size_t)p*T_ + t0) * OUT_;
    for (int i = tid; i < 64*OUT_; i += 512) {
        int t = i / OUT_;
        int o = i - t*OUT_;
        u64 acc = 0ull;
        const float* arow = AB + t*ASTRIDE;
        const float* wrow = W4 + o*33;
        #pragma unroll
        for (int k = 0; k < 32; k += 2)
            acc = fma2(*(const u64*)(arow + k), pack2(wrow[k], wrow[k+1]), acc);
        op[i] = sum2(acc) + B4[o];
    }
}

// ---------------------------------------------------------------------------
extern "C" void kernel_launch(void* const* d_in, const int* in_sizes, int n_in,
                              void* d_out, int out_size)
{
    const float* z    = (const float*)d_in[0];
    const float* w_ih = (const float*)d_in[1];
    const float* w_hh = (const float*)d_in[2];
    const float* b_ih = (const float*)d_in[3];
    const float* b_hh = (const float*)d_in[4];
    const float* w1   = (const float*)d_in[5];
    const float* b1   = (const float*)d_in[6];
    const float* w2   = (const float*)d_in[7];
    const float* b2   = (const float*)d_in[8];
    const float* w3   = (const float*)d_in[9];
    const float* b3   = (const float*)d_in[10];
    const float* w4   = (const float*)d_in[11];
    const float* b4   = (const float*)d_in[12];
    float* out = (float*)d_out;

    const int xproj_smem = XPROJ_SMEM_FLOATS * 4;   // ~132 KB
    const int mlp_smem   = MLP_SMEM_FLOATS  * 4;    // ~146 KB
    cudaFuncSetAttribute(xproj_kernel, cudaFuncAttributeMaxDynamicSharedMemorySize, xproj_smem);
    cudaFuncSetAttribute(mlp_kernel,   cudaFuncAttributeMaxDynamicSharedMemorySize, mlp_smem);

    xproj_kernel<<<dim3(T_/64, P_), 512, xproj_smem>>>(z, w_ih, b_ih);
    gru_kernel<<<P_, 192>>>(w_hh, b_hh);
    mlp_kernel<<<dim3(T_/64, P_), 512, mlp_smem>>>(w1, b1, w2, b2, w3, b3, w4, b4, out);
}

// round 10
// speedup vs baseline: 1.5257x; 1.3716x over previous
#include <cuda_runtime.h>
#include <math.h>

#define P_   128
#define T_   2048
#define D_   128
#define H_   64
#define G_   192   // 3*H
#define OUT_ 24

typedef unsigned long long u64;

// Scratch (device global: allocation-free per harness rules)
static __device__ float g_hs[(size_t)P_ * T_ * H_];  // [P][T][64]

// ---- packed f32x2 helpers -------------------------------------------------
__device__ __forceinline__ u64 fma2(u64 a, u64 b, u64 c) {
    u64 d; asm("fma.rn.f32x2 %0, %1, %2, %3;" : "=l"(d) : "l"(a), "l"(b), "l"(c));
    return d;
}
__device__ __forceinline__ u64 pack2(float lo, float hi) {
    u64 r; asm("mov.b64 %0, {%1, %2};" : "=l"(r) : "f"(lo), "f"(hi));
    return r;
}
__device__ __forceinline__ float sum2(u64 v) {
    float lo, hi; asm("mov.b64 {%0, %1}, %2;" : "=f"(lo), "=f"(hi) : "l"(v));
    return lo + hi;
}
// fast sigmoid / tanh (ex2.approx + rcp.approx; ~1e-6 rel err vs 1e-3 budget)
__device__ __forceinline__ float sigf(float x) {
    return __fdividef(1.f, 1.f + __expf(-x));
}
__device__ __forceinline__ float tanhfast(float x) {
    return 2.f * __fdividef(1.f, 1.f + __expf(-2.f * x)) - 1.f;
}

// ---------------------------------------------------------------------------
// Kernel 1: FUSED x_proj + GRU recurrence. 1 CTA per part, 192 threads.
// Thread j keeps w_ih[j][:] (64 u64) AND w_hh[j][:] (32 u64) in registers.
// z streamed via cp.async double-buffered 32-step tiles (prefetch ~32 steps).
// ---------------------------------------------------------------------------
#define ZTILE 32
#define NTILES (T_ / ZTILE)   // 64

__global__ __launch_bounds__(192, 1)
void gru_fused_kernel(const float* __restrict__ z,
                      const float* __restrict__ w_ih,
                      const float* __restrict__ b_ih,
                      const float* __restrict__ w_hh,
                      const float* __restrict__ b_hh)
{
    __shared__ __align__(16) float zbuf[2][ZTILE * D_];   // 2 x 16 KB
    __shared__ __align__(16) float h_sh[H_];
    __shared__ float s1[192];   // xp + hp (r,z gates)
    __shared__ float s2[64];    // hp of n-gate
    __shared__ float s3[64];    // xp of n-gate

    const int j = threadIdx.x;
    const int p = blockIdx.x;

    // per-thread weight rows in registers
    u64 wih[64];
    {
        const ulonglong2* wp = (const ulonglong2*)(w_ih + ((size_t)p*G_ + j) * D_);
        #pragma unroll
        for (int q = 0; q < 32; q++) { ulonglong2 v = wp[q]; wih[2*q] = v.x; wih[2*q+1] = v.y; }
    }
    u64 whh[32];
    {
        const ulonglong2* wp = (const ulonglong2*)(w_hh + ((size_t)p*G_ + j) * H_);
        #pragma unroll
        for (int q = 0; q < 16; q++) { ulonglong2 v = wp[q]; whh[2*q] = v.x; whh[2*q+1] = v.y; }
    }
    const float bih = b_ih[p*G_ + j];
    const float bhh = b_hh[p*G_ + j];

    if (j < 64) h_sh[j] = 0.f;

    const float* zp = z + (size_t)p * T_ * D_;

    // prologue: async-load tiles 0 and 1
    #pragma unroll 1
    for (int tl = 0; tl < 2; tl++) {
        const float* src = zp + (size_t)tl * ZTILE * D_;
        for (int i = j; i < ZTILE * D_ / 4; i += 192) {
            unsigned dst = (unsigned)__cvta_generic_to_shared(&zbuf[tl][i*4]);
            asm volatile("cp.async.cg.shared.global [%0], [%1], 16;"
                         :: "r"(dst), "l"(src + i*4));
        }
        asm volatile("cp.async.commit_group;");
    }

    float* hout = g_hs + (size_t)p * T_ * H_;

    for (int tile = 0; tile < NTILES; tile++) {
        // wait for this tile's buffer (last tile: no younger group may remain)
        if (tile < NTILES - 1) asm volatile("cp.async.wait_group 1;");
        else                   asm volatile("cp.async.wait_group 0;");
        __syncthreads();

        const float* zt = zbuf[tile & 1];

        for (int s = 0; s < ZTILE; s++) {
            // x-projection dot: 128-wide, broadcast z row from smem
            u64 x0 = 0ull, x1 = 0ull, x2 = 0ull, x3 = 0ull;
            const ulonglong2* zr = (const ulonglong2*)(zt + s * D_);
            #pragma unroll
            for (int q = 0; q < 16; q++) {
                ulonglong2 a0 = zr[2*q], a1 = zr[2*q+1];
                x0 = fma2(wih[4*q+0], a0.x, x0);
                x1 = fma2(wih[4*q+1], a0.y, x1);
                x2 = fma2(wih[4*q+2], a1.x, x2);
                x3 = fma2(wih[4*q+3], a1.y, x3);
            }
            float xp = (sum2(x0) + sum2(x1)) + (sum2(x2) + sum2(x3)) + bih;

            // hidden dot: 64-wide
            u64 a0 = 0ull, a1 = 0ull, a2 = 0ull, a3 = 0ull;
            const ulonglong2* hr = (const ulonglong2*)h_sh;
            #pragma unroll
            for (int q = 0; q < 8; q++) {
                ulonglong2 h0 = hr[2*q], h1 = hr[2*q+1];
                a0 = fma2(whh[4*q+0], h0.x, a0);
                a1 = fma2(whh[4*q+1], h0.y, a1);
                a2 = fma2(whh[4*q+2], h1.x, a2);
                a3 = fma2(whh[4*q+3], h1.y, a3);
            }
            float hp = (sum2(a0) + sum2(a1)) + (sum2(a2) + sum2(a3)) + bhh;

            s1[j] = xp + hp;
            if (j >= 128) { s2[j - 128] = hp; s3[j - 128] = xp; }
            __syncthreads();

            if (j < 64) {
                float r = sigf(s1[j]);
                float u = sigf(s1[j + 64]);
                float n = tanhfast(s3[j] + r * s2[j]);
                float hv = n + u * (h_sh[j] - n);
                h_sh[j] = hv;
                hout[(size_t)(tile*ZTILE + s) * H_ + j] = hv;
            }
            __syncthreads();
        }

        // refill the buffer we just consumed with tile+2
        if (tile + 2 < NTILES) {
            const float* src = zp + (size_t)(tile + 2) * ZTILE * D_;
            for (int i = j; i < ZTILE * D_ / 4; i += 192) {
                unsigned dst = (unsigned)__cvta_generic_to_shared(&zbuf[tile & 1][i*4]);
                asm volatile("cp.async.cg.shared.global [%0], [%1], 16;"
                             :: "r"(dst), "l"(src + i*4));
            }
            asm volatile("cp.async.commit_group;");
        }
    }
}

// ---------------------------------------------------------------------------
// Kernel 2: fused 4-layer MLP. Grid (64, P), 256 threads, 32-row tiles.
// smem ~112.6 KB -> 2 CTAs/SM. Weights natural [o][k], odd stride.
// ---------------------------------------------------------------------------
#define ASTRIDE 132
#define TROWS   32
#define MLP_SMEM_FLOATS (128*65 + 64*129 + 32*65 + 24*33 + 128 + 64 + 32 + 24 + 2*TROWS*ASTRIDE)

template<int I, int O, bool RELU>
__device__ __forceinline__
void mlp_layer(int tid, const float* __restrict__ ain, float* __restrict__ aout,
               const float* __restrict__ W, const float* __restrict__ bias)
{
    constexpr int OGN  = O / 4;          // 32 / 16 / 8
    constexpr int ROWS = OGN / 8;        // 4  / 2  / 1   (TGN*ROWS = 32)
    constexpr int WS   = I + 1;

    const int og = tid % OGN;
    const int tg = tid / OGN;

    u64 acc[ROWS][4];
    #pragma unroll
    for (int r = 0; r < ROWS; r++)
        #pragma unroll
        for (int c = 0; c < 4; c++) acc[r][c] = 0ull;

    const float* arow = ain + tg*ROWS*ASTRIDE;

    #pragma unroll 8
    for (int k = 0; k < I; k += 2) {
        u64 av[ROWS];
        #pragma unroll
        for (int r = 0; r < ROWS; r++)
            av[r] = *(const u64*)(arow + r*ASTRIDE + k);
        #pragma unroll
        for (int c = 0; c < 4; c++) {
            const float* wrow = W + (og + c*OGN)*WS + k;
            u64 bv = pack2(wrow[0], wrow[1]);
            #pragma unroll
            for (int r = 0; r < ROWS; r++)
                acc[r][c] = fma2(av[r], bv, acc[r][c]);
        }
    }

    #pragma unroll
    for (int r = 0; r < ROWS; r++)
        #pragma unroll
        for (int c = 0; c < 4; c++) {
            int o = og + c*OGN;
            float v = sum2(acc[r][c]) + bias[o];
            if (RELU) v = fmaxf(v, 0.f);
            aout[(tg*ROWS + r)*ASTRIDE + o] = v;
        }
}

__global__ __launch_bounds__(256, 2)
void mlp_kernel(const float* __restrict__ w1, const float* __restrict__ b1,
                const float* __restrict__ w2, const float* __restrict__ b2,
                const float* __restrict__ w3, const float* __restrict__ b3,
                const float* __restrict__ w4, const float* __restrict__ b4,
                float* __restrict__ out)
{
    extern __shared__ float sm[];
    float* W1 = sm;                 // 128 x 65
    float* W2 = W1 + 128*65;        // 64  x 129
    float* W3 = W2 + 64*129;        // 32  x 65
    float* W4 = W3 + 32*65;         // 24  x 33
    float* B1 = W4 + 24*33;
    float* B2 = B1 + 128;
    float* B3 = B2 + 64;
    float* B4 = B3 + 32;
    float* AA = B4 + 24;            // 32 x 132
    float* AB = AA + TROWS*ASTRIDE; // 32 x 132

    const int tid = threadIdx.x;
    const int p   = blockIdx.y;
    const int t0  = blockIdx.x * TROWS;

    {
        const float* wp = w1 + (size_t)p*128*64;
        for (int i = tid; i < 128*64; i += 256) { int o = i >> 6, k = i & 63;  W1[o*65  + k] = wp[i]; }
        wp = w2 + (size_t)p*64*128;
        for (int i = tid; i < 64*128; i += 256) { int o = i >> 7, k = i & 127; W2[o*129 + k] = wp[i]; }
        wp = w3 + (size_t)p*32*64;
        for (int i = tid; i < 32*64;  i += 256) { int o = i >> 6, k = i & 63;  W3[o*65  + k] = wp[i]; }
        wp = w4 + (size_t)p*24*32;
        for (int i = tid; i < 24*32;  i += 256) { int o = i >> 5, k = i & 31;  W4[o*33  + k] = wp[i]; }
    }
    if (tid < 128) B1[tid] = b1[p*128 + tid];
    if (tid < 64)  B2[tid] = b2[p*64  + tid];
    if (tid < 32)  B3[tid] = b3[p*32  + tid];
    if (tid < 24)  B4[tid] = b4[p*24  + tid];

    {   // hidden-state tile -> AA
        const float* hp = g_hs + ((size_t)p*T_ + t0) * H_;
        for (int i = tid; i < TROWS*64; i += 256) { int t = i >> 6, k = i & 63; AA[t*ASTRIDE + k] = hp[i]; }
    }
    __syncthreads();

    mlp_layer<64, 128, true>(tid, AA, AB, W1, B1);
    __syncthreads();
    mlp_layer<128, 64, true>(tid, AB, AA, W2, B2);
    __syncthreads();
    mlp_layer<64, 32, true>(tid, AA, AB, W3, B3);
    __syncthreads();

    // layer 4 (32 -> 24, no relu)
    float* op = out + ((size_t)p*T_ + t0) * OUT_;
    for (int i = tid; i < TROWS*OUT_; i += 256) {
        int t = i / OUT_;
        int o = i - t*OUT_;
        u64 acc = 0ull;
        const float* arow = AB + t*ASTRIDE;
        const float* wrow = W4 + o*33;
        #pragma unroll
        for (int k = 0; k < 32; k += 2)
            acc = fma2(*(const u64*)(arow + k), pack2(wrow[k], wrow[k+1]), acc);
        op[i] = sum2(acc) + B4[o];
    }
}

// ---------------------------------------------------------------------------
extern "C" void kernel_launch(void* const* d_in, const int* in_sizes, int n_in,
                              void* d_out, int out_size)
{
    const float* z    = (const float*)d_in[0];
    const float* w_ih = (const float*)d_in[1];
    const float* w_hh = (const float*)d_in[2];
    const float* b_ih = (const float*)d_in[3];
    const float* b_hh = (const float*)d_in[4];
    const float* w1   = (const float*)d_in[5];
    const float* b1   = (const float*)d_in[6];
    const float* w2   = (const float*)d_in[7];
    const float* b2   = (const float*)d_in[8];
    const float* w3   = (const float*)d_in[9];
    const float* b3   = (const float*)d_in[10];
    const float* w4   = (const float*)d_in[11];
    const float* b4   = (const float*)d_in[12];
    float* out = (float*)d_out;

    const int mlp_smem = MLP_SMEM_FLOATS * 4;   // ~112.6 KB -> 2 CTAs/SM
    cudaFuncSetAttribute(mlp_kernel, cudaFuncAttributeMaxDynamicSharedMemorySize, mlp_smem);

    gru_fused_kernel<<<P_, 192>>>(z, w_ih, b_ih, w_hh, b_hh);
    mlp_kernel<<<dim3(T_/TROWS, P_), 256, mlp_smem>>>(w1, b1, w2, b2, w3, b3, w4, b4, out);
}

// round 11
// speedup vs baseline: 2.1900x; 1.4355x over previous
#include <cuda_runtime.h>
#include <math.h>

#define P_   128
#define T_   2048
#define D_   128
#define H_   64
#define G_   192   // 3*H
#define OUT_ 24

typedef unsigned long long u64;

// Scratch (device global: allocation-free per harness rules)
static __device__ float g_hs[(size_t)P_ * T_ * H_];  // [P][T][64]

// ---- packed f32x2 + activation helpers ------------------------------------
__device__ __forceinline__ u64 fma2(u64 a, u64 b, u64 c) {
    u64 d; asm("fma.rn.f32x2 %0, %1, %2, %3;" : "=l"(d) : "l"(a), "l"(b), "l"(c));
    return d;
}
__device__ __forceinline__ u64 pack2(float lo, float hi) {
    u64 r; asm("mov.b64 %0, {%1, %2};" : "=l"(r) : "f"(lo), "f"(hi));
    return r;
}
__device__ __forceinline__ float sum2(u64 v) {
    float lo, hi; asm("mov.b64 {%0, %1}, %2;" : "=f"(lo), "=f"(hi) : "l"(v));
    return lo + hi;
}
__device__ __forceinline__ float tanhapx(float x) {
    float y; asm("tanh.approx.f32 %0, %1;" : "=f"(y) : "f"(x)); return y;
}

// named barriers (memory-clobbered)
#define NB_SYNC(id, cnt)   asm volatile("bar.sync %0, %1;"   :: "r"(id), "r"(cnt) : "memory")
#define NB_ARRIVE(id, cnt) asm volatile("bar.arrive %0, %1;" :: "r"(id), "r"(cnt) : "memory")

// ---------------------------------------------------------------------------
// One persistent CTA per part, 384 threads.
// Phase 1 (GRU): threads 0-191 = consumers (serial recurrence),
//                threads 192-383 = producers (x-projection into smem ring).
// Phase 2 (MLP): 3 groups x 128 threads pipeline 32-row tiles.
// ---------------------------------------------------------------------------
#define ZTILE  32
#define NTILES (T_ / ZTILE)   // 64

// GRU smem layout (floats)
#define SM_ZBUF   0                       // 2 * 32*128 = 8192
#define SM_XP     (SM_ZBUF + 8192)        // 2 * 32*192 = 12288
#define SM_H      (SM_XP + 12288)         // 64
#define SM_S1     (SM_H + 64)             // 192
#define SM_S2     (SM_S1 + 192)           // 64
#define SM_S3     (SM_S2 + 64)            // 64
#define SM_GRU_TOTAL (SM_S3 + 64)         // 20864 floats

// MLP smem layout (floats) — reuses the same region after phase 1
#define SM_W1   0                         // 128*65 = 8320
#define SM_W2   (SM_W1 + 128*65)          // 64*129 = 8256
#define SM_W3   (SM_W2 + 64*129)          // 32*65  = 2080
#define SM_W4   (SM_W3 + 32*65)           // 24*33  = 792
#define SM_B1   (SM_W4 + 24*33)
#define SM_B2   (SM_B1 + 128)
#define SM_B3   (SM_B2 + 64)
#define SM_B4   (SM_B3 + 32)
#define SM_ACT  (SM_B4 + 24)              // 19696; 3 groups * 2 * 32*132
#define ASTRIDE 132
#define ACT_PER_GRP (2 * 32 * ASTRIDE)    // 8448
#define SM_MLP_TOTAL (SM_ACT + 3*ACT_PER_GRP)  // 45040 floats

#define SM_TOTAL_FLOATS (SM_MLP_TOTAL > SM_GRU_TOTAL ? SM_MLP_TOTAL : SM_GRU_TOTAL)

// --- 128-thread, 32-row MLP layer -----------------------------------------
template<int I, int O, bool RELU>
__device__ __forceinline__
void mlp_layer128(int lt, const float* __restrict__ ain, float* __restrict__ aout,
                  const float* __restrict__ W, const float* __restrict__ bias)
{
    constexpr int OGN  = O / 4;           // 32 / 16 / 8
    constexpr int TGN  = 128 / OGN;       // 4 / 8 / 16
    constexpr int ROWS = 32 / TGN;        // 8 / 4 / 2
    constexpr int WS   = I + 1;           // odd stride -> conflict-free

    const int og = lt % OGN;
    const int tg = lt / OGN;

    u64 acc[ROWS][4];
    #pragma unroll
    for (int r = 0; r < ROWS; r++)
        #pragma unroll
        for (int c = 0; c < 4; c++) acc[r][c] = 0ull;

    const float* arow = ain + tg*ROWS*ASTRIDE;

    #pragma unroll 8
    for (int k = 0; k < I; k += 2) {
        u64 av[ROWS];
        #pragma unroll
        for (int r = 0; r < ROWS; r++)
            av[r] = *(const u64*)(arow + r*ASTRIDE + k);
        #pragma unroll
        for (int c = 0; c < 4; c++) {
            const float* wrow = W + (og + c*OGN)*WS + k;
            u64 bv = pack2(wrow[0], wrow[1]);
            #pragma unroll
            for (int r = 0; r < ROWS; r++)
                acc[r][c] = fma2(av[r], bv, acc[r][c]);
        }
    }

    #pragma unroll
    for (int r = 0; r < ROWS; r++)
        #pragma unroll
        for (int c = 0; c < 4; c++) {
            int o = og + c*OGN;
            float v = sum2(acc[r][c]) + bias[o];
            if (RELU) v = fmaxf(v, 0.f);
            aout[(tg*ROWS + r)*ASTRIDE + o] = v;
        }
}

__global__ __launch_bounds__(384, 1)
void decoder_kernel(const float* __restrict__ z,
                    const float* __restrict__ w_ih,
                    const float* __restrict__ b_ih,
                    const float* __restrict__ w_hh,
                    const float* __restrict__ b_hh,
                    const float* __restrict__ w1, const float* __restrict__ b1,
                    const float* __restrict__ w2, const float* __restrict__ b2,
                    const float* __restrict__ w3, const float* __restrict__ b3,
                    const float* __restrict__ w4, const float* __restrict__ b4,
                    float* __restrict__ out)
{
    extern __shared__ __align__(16) float sm[];
    const int tid = threadIdx.x;
    const int p   = blockIdx.x;

    float* hout = g_hs + (size_t)p * T_ * H_;

    // =======================================================================
    // Phase 1: GRU (producer/consumer)
    // =======================================================================
    if (tid < 192) {
        // -------- consumer: serial recurrence --------
        const int j = tid;
        u64 whh[32];
        {
            const ulonglong2* wp = (const ulonglong2*)(w_hh + ((size_t)p*G_ + j) * H_);
            #pragma unroll
            for (int q = 0; q < 16; q++) { ulonglong2 v = wp[q]; whh[2*q] = v.x; whh[2*q+1] = v.y; }
        }
        const float bhh = b_hh[p*G_ + j];

        float* h_sh = sm + SM_H;
        float* s1   = sm + SM_S1;
        float* s2   = sm + SM_S2;
        float* s3   = sm + SM_S3;

        if (j < 64) h_sh[j] = 0.f;
        NB_SYNC(1, 192);

        for (int tile = 0; tile < NTILES; tile++) {
            const int st = tile & 1;
            NB_SYNC(3 + st, 384);                       // wait xp tile full
            const float* xt = sm + SM_XP + st * (ZTILE * 192);

            for (int s = 0; s < ZTILE; s++) {
                u64 a0 = 0ull, a1 = 0ull, a2 = 0ull, a3 = 0ull;
                const ulonglong2* hr = (const ulonglong2*)h_sh;
                #pragma unroll
                for (int q = 0; q < 8; q++) {
                    ulonglong2 h0 = hr[2*q], h1 = hr[2*q+1];
                    a0 = fma2(whh[4*q+0], h0.x, a0);
                    a1 = fma2(whh[4*q+1], h0.y, a1);
                    a2 = fma2(whh[4*q+2], h1.x, a2);
                    a3 = fma2(whh[4*q+3], h1.y, a3);
                }
                float hp = (sum2(a0) + sum2(a1)) + (sum2(a2) + sum2(a3)) + bhh;
                float xp = xt[s*192 + j];

                s1[j] = xp + hp;
                if (j >= 128) { s2[j - 128] = hp; s3[j - 128] = xp; }
                NB_SYNC(1, 192);

                if (j < 64) {
                    float r = 0.5f + 0.5f * tanhapx(0.5f * s1[j]);
                    float u = 0.5f + 0.5f * tanhapx(0.5f * s1[j + 64]);
                    float n = tanhapx(s3[j] + r * s2[j]);
                    float hv = n + u * (h_sh[j] - n);
                    h_sh[j] = hv;
                    hout[(size_t)(tile*ZTILE + s) * H_ + j] = hv;
                }
                NB_SYNC(1, 192);
            }
            NB_ARRIVE(5 + st, 384);                     // release xp tile
        }
    } else {
        // -------- producer: x-projection --------
        const int j = tid - 192;
        u64 wih[64];
        {
            const ulonglong2* wp = (const ulonglong2*)(w_ih + ((size_t)p*G_ + j) * D_);
            #pragma unroll
            for (int q = 0; q < 32; q++) { ulonglong2 v = wp[q]; wih[2*q] = v.x; wih[2*q+1] = v.y; }
        }
        const float bih = b_ih[p*G_ + j];
        const float* zp = z + (size_t)p * T_ * D_;

        // prologue: async-load z tiles 0 and 1
        #pragma unroll 1
        for (int tl = 0; tl < 2; tl++) {
            const float* src = zp + (size_t)tl * ZTILE * D_;
            for (int i = j; i < ZTILE * D_ / 4; i += 192) {
                unsigned dst = (unsigned)__cvta_generic_to_shared(sm + SM_ZBUF + tl*(ZTILE*D_) + i*4);
                asm volatile("cp.async.cg.shared.global [%0], [%1], 16;" :: "r"(dst), "l"(src + i*4));
            }
            asm volatile("cp.async.commit_group;");
        }

        for (int tile = 0; tile < NTILES; tile++) {
            const int st = tile & 1;
            if (tile < NTILES - 1) asm volatile("cp.async.wait_group 1;");
            else                   asm volatile("cp.async.wait_group 0;");
            NB_SYNC(2, 192);                            // z tile visible to all producers
            if (tile >= 2) NB_SYNC(5 + st, 384);        // wait xp tile empty

            float*       xt = sm + SM_XP   + st * (ZTILE * 192);
            const float* zt = sm + SM_ZBUF + st * (ZTILE * D_);

            for (int s = 0; s < ZTILE; s++) {
                u64 x0 = 0ull, x1 = 0ull, x2 = 0ull, x3 = 0ull;
                const ulonglong2* zr = (const ulonglong2*)(zt + s * D_);
                #pragma unroll
                for (int q = 0; q < 16; q++) {
                    ulonglong2 a0v = zr[2*q], a1v = zr[2*q+1];
                    x0 = fma2(wih[4*q+0], a0v.x, x0);
                    x1 = fma2(wih[4*q+1], a0v.y, x1);
                    x2 = fma2(wih[4*q+2], a1v.x, x2);
                    x3 = fma2(wih[4*q+3], a1v.y, x3);
                }
                xt[s*192 + j] = (sum2(x0) + sum2(x1)) + (sum2(x2) + sum2(x3)) + bih;
            }
            NB_ARRIVE(3 + st, 384);                     // publish xp tile

            if (tile + 2 < NTILES) {                    // refill consumed z buffer
                const float* src = zp + (size_t)(tile + 2) * ZTILE * D_;
                for (int i = j; i < ZTILE * D_ / 4; i += 192) {
                    unsigned dst = (unsigned)__cvta_generic_to_shared(sm + SM_ZBUF + st*(ZTILE*D_) + i*4);
                    asm volatile("cp.async.cg.shared.global [%0], [%1], 16;" :: "r"(dst), "l"(src + i*4));
                }
                asm volatile("cp.async.commit_group;");
            }
        }
    }

    __syncthreads();   // phase boundary: g_hs writes visible; smem repurposed

    // =======================================================================
    // Phase 2: MLP (weights loaded once per part; 3 groups x 128 threads)
    // =======================================================================
    float* W1 = sm + SM_W1;  float* W2 = sm + SM_W2;
    float* W3 = sm + SM_W3;  float* W4 = sm + SM_W4;
    float* B1 = sm + SM_B1;  float* B2 = sm + SM_B2;
    float* B3 = sm + SM_B3;  float* B4 = sm + SM_B4;

    {
        const float* wp = w1 + (size_t)p*128*64;
        for (int i = tid; i < 128*64; i += 384) { int o = i >> 6, k = i & 63;  W1[o*65  + k] = wp[i]; }
        wp = w2 + (size_t)p*64*128;
        for (int i = tid; i < 64*128; i += 384) { int o = i >> 7, k = i & 127; W2[o*129 + k] = wp[i]; }
        wp = w3 + (size_t)p*32*64;
        for (int i = tid; i < 32*64;  i += 384) { int o = i >> 6, k = i & 63;  W3[o*65  + k] = wp[i]; }
        wp = w4 + (size_t)p*24*32;
        for (int i = tid; i < 24*32;  i += 384) { int o = i >> 5, k = i & 31;  W4[o*33  + k] = wp[i]; }
    }
    if (tid < 128)                 B1[tid]       = b1[p*128 + tid];
    if (tid >= 128 && tid < 192)   B2[tid - 128] = b2[p*64 + tid - 128];
    if (tid >= 192 && tid < 224)   B3[tid - 192] = b3[p*32 + tid - 192];
    if (tid >= 224 && tid < 248)   B4[tid - 224] = b4[p*24 + tid - 224];
    __syncthreads();

    const int g  = tid >> 7;        // group 0..2
    const int lt = tid & 127;
    float* AA = sm + SM_ACT + g * ACT_PER_GRP;
    float* AB = AA + 32 * ASTRIDE;

    for (int tile = g; tile < T_ / 32; tile += 3) {
        // load 32x64 hidden rows -> AA (float4, coalesced)
        {
            const float4* hp4 = (const float4*)(g_hs + ((size_t)p*T_ + tile*32) * H_);
            for (int i = lt; i < 32*16; i += 128) {
                int t = i >> 4, kq = i & 15;
                *(float4*)(AA + t*ASTRIDE + kq*4) = hp4[i];
            }
        }
        NB_SYNC(8 + g, 128);

        mlp_layer128<64, 128, true>(lt, AA, AB, W1, B1);
        NB_SYNC(8 + g, 128);
        mlp_layer128<128, 64, true>(lt, AB, AA, W2, B2);
        NB_SYNC(8 + g, 128);
        mlp_layer128<64, 32, true>(lt, AA, AB, W3, B3);
        NB_SYNC(8 + g, 128);

        // layer 4: 32 -> 24, no relu
        float* op = out + ((size_t)p*T_ + tile*32) * OUT_;
        for (int i = lt; i < 32*OUT_; i += 128) {
            int t = i / OUT_;
            int o = i - t*OUT_;
            u64 acc = 0ull;
            const float* arow = AB + t*ASTRIDE;
            const float* wrow = W4 + o*33;
            #pragma unroll
            for (int k = 0; k < 32; k += 2)
                acc = fma2(*(const u64*)(arow + k), pack2(wrow[k], wrow[k+1]), acc);
            op[i] = sum2(acc) + B4[o];
        }
        NB_SYNC(8 + g, 128);
    }
}

// ---------------------------------------------------------------------------
extern "C" void kernel_launch(void* const* d_in, const int* in_sizes, int n_in,
                              void* d_out, int out_size)
{
    const float* z    = (const float*)d_in[0];
    const float* w_ih = (const float*)d_in[1];
    const float* w_hh = (const float*)d_in[2];
    const float* b_ih = (const float*)d_in[3];
    const float* b_hh = (const float*)d_in[4];
    const float* w1   = (const float*)d_in[5];
    const float* b1   = (const float*)d_in[6];
    const float* w2   = (const float*)d_in[7];
    const float* b2   = (const float*)d_in[8];
    const float* w3   = (const float*)d_in[9];
    const float* b3   = (const float*)d_in[10];
    const float* w4   = (const float*)d_in[11];
    const float* b4   = (const float*)d_in[12];
    float* out = (float*)d_out;

    const int smem_bytes = SM_TOTAL_FLOATS * 4;   // 180160 B
    cudaFuncSetAttribute(decoder_kernel, cudaFuncAttributeMaxDynamicSharedMemorySize, smem_bytes);

    decoder_kernel<<<P_, 384, smem_bytes>>>(z, w_ih, b_ih, w_hh, b_hh,
                                            w1, b1, w2, b2, w3, b3, w4, b4, out);
}

// round 12
// speedup vs baseline: 2.3849x; 1.0890x over previous
#include <cuda_runtime.h>
#include <math.h>

#define P_   128
#define T_   2048
#define D_   128
#define H_   64
#define G_   192   // 3*H
#define OUT_ 24

typedef unsigned long long u64;

// Scratch (device global: allocation-free per harness rules)
static __device__ float g_hs[(size_t)P_ * T_ * H_];  // [P][T][64]

// ---- packed f32x2 + activation helpers ------------------------------------
__device__ __forceinline__ u64 fma2(u64 a, u64 b, u64 c) {
    u64 d; asm("fma.rn.f32x2 %0, %1, %2, %3;" : "=l"(d) : "l"(a), "l"(b), "l"(c));
    return d;
}
__device__ __forceinline__ u64 pack2(float lo, float hi) {
    u64 r; asm("mov.b64 %0, {%1, %2};" : "=l"(r) : "f"(lo), "f"(hi));
    return r;
}
__device__ __forceinline__ float sum2(u64 v) {
    float lo, hi; asm("mov.b64 {%0, %1}, %2;" : "=f"(lo), "=f"(hi) : "l"(v));
    return lo + hi;
}
__device__ __forceinline__ float tanhapx(float x) {
    float y; asm("tanh.approx.f32 %0, %1;" : "=f"(y) : "f"(x)); return y;
}

// named barriers (memory-clobbered)
#define NB_SYNC(id, cnt)   asm volatile("bar.sync %0, %1;"   :: "r"(id), "r"(cnt) : "memory")
#define NB_ARRIVE(id, cnt) asm volatile("bar.arrive %0, %1;" :: "r"(id), "r"(cnt) : "memory")

// ===========================================================================
// Kernel A: fused x_proj + GRU. 1 CTA/part, 384 threads.
//   threads 0-191  : consumers (recurrence). warps 0-1 activate; 2-5 arrive.
//   threads 192-383: producers (x-projection into 2-stage smem ring).
// ===========================================================================
#define ZTILE  32
#define NTILES (T_ / ZTILE)   // 64

#define SM_ZBUF   0                       // 2 * 32*128 = 8192
#define SM_XP     (SM_ZBUF + 8192)        // 2 * 32*192 = 12288
#define SM_H      (SM_XP + 12288)         // 64
#define SM_S1     (SM_H + 64)             // 192
#define SM_S2     (SM_S1 + 192)           // 64
#define SM_S3     (SM_S2 + 64)            // 64
#define SM_GRU_TOTAL (SM_S3 + 64)         // 20864 floats = 83456 B

__global__ __launch_bounds__(384, 1)
void gru_kernel(const float* __restrict__ z,
                const float* __restrict__ w_ih,
                const float* __restrict__ b_ih,
                const float* __restrict__ w_hh,
                const float* __restrict__ b_hh)
{
    extern __shared__ __align__(16) float sm[];
    const int tid = threadIdx.x;
    const int p   = blockIdx.x;
    float* hout = g_hs + (size_t)p * T_ * H_;

    if (tid < 192) {
        // ---------------- consumer ----------------
        const int j = tid;
        u64 whh[32];
        {
            const ulonglong2* wp = (const ulonglong2*)(w_hh + ((size_t)p*G_ + j) * H_);
            #pragma unroll
            for (int q = 0; q < 16; q++) { ulonglong2 v = wp[q]; whh[2*q] = v.x; whh[2*q+1] = v.y; }
        }
        const float bhh = b_hh[p*G_ + j];

        float* h_sh = sm + SM_H;
        float* s1   = sm + SM_S1;
        float* s2   = sm + SM_S2;
        float* s3   = sm + SM_S3;

        if (j < 64) h_sh[j] = 0.f;
        NB_SYNC(1, 192);

        for (int tile = 0; tile < NTILES; tile++) {
            const int st = tile & 1;
            NB_SYNC(3 + st, 384);                       // xp tile full
            const float* xt = sm + SM_XP + st * (ZTILE * 192);

            for (int s = 0; s < ZTILE; s++) {
                u64 a0 = 0ull, a1 = 0ull, a2 = 0ull, a3 = 0ull;
                const ulonglong2* hr = (const ulonglong2*)h_sh;
                #pragma unroll
                for (int q = 0; q < 8; q++) {
                    ulonglong2 h0 = hr[2*q], h1 = hr[2*q+1];
                    a0 = fma2(whh[4*q+0], h0.x, a0);
                    a1 = fma2(whh[4*q+1], h0.y, a1);
                    a2 = fma2(whh[4*q+2], h1.x, a2);
                    a3 = fma2(whh[4*q+3], h1.y, a3);
                }
                float hp = (sum2(a0) + sum2(a1)) + (sum2(a2) + sum2(a3)) + bhh;
                float xp = xt[s*192 + j];

                if (j >= 64) {
                    if (j < 128) s1[j] = xp + hp;                 // z gate
                    else         { s2[j - 128] = hp; s3[j - 128] = xp; }  // n gate
                    NB_ARRIVE(7, 192);
                    NB_SYNC(8, 192);                    // wait for new h
                } else {
                    const float pre_r = xp + hp;        // own r pre-act in reg
                    NB_SYNC(7, 192);                    // wait z,n data
                    float r = 0.5f + 0.5f * tanhapx(0.5f * pre_r);
                    float u = 0.5f + 0.5f * tanhapx(0.5f * s1[j + 64]);
                    float n = tanhapx(s3[j] + r * s2[j]);
                    float hv = n + u * (h_sh[j] - n);
                    h_sh[j] = hv;
                    hout[(size_t)(tile*ZTILE + s) * H_ + j] = hv;
                    NB_SYNC(8, 192);                    // publish h
                }
            }
            NB_ARRIVE(5 + st, 384);                     // release xp tile
        }
    } else {
        // ---------------- producer ----------------
        const int j = tid - 192;
        u64 wih[64];
        {
            const ulonglong2* wp = (const ulonglong2*)(w_ih + ((size_t)p*G_ + j) * D_);
            #pragma unroll
            for (int q = 0; q < 32; q++) { ulonglong2 v = wp[q]; wih[2*q] = v.x; wih[2*q+1] = v.y; }
        }
        const float bih = b_ih[p*G_ + j];
        const float* zp = z + (size_t)p * T_ * D_;

        #pragma unroll 1
        for (int tl = 0; tl < 2; tl++) {                // prologue: z tiles 0,1
            const float* src = zp + (size_t)tl * ZTILE * D_;
            for (int i = j; i < ZTILE * D_ / 4; i += 192) {
                unsigned dst = (unsigned)__cvta_generic_to_shared(sm + SM_ZBUF + tl*(ZTILE*D_) + i*4);
                asm volatile("cp.async.cg.shared.global [%0], [%1], 16;" :: "r"(dst), "l"(src + i*4));
            }
            asm volatile("cp.async.commit_group;");
        }

        for (int tile = 0; tile < NTILES; tile++) {
            const int st = tile & 1;
            if (tile < NTILES - 1) asm volatile("cp.async.wait_group 1;");
            else                   asm volatile("cp.async.wait_group 0;");
            NB_SYNC(2, 192);                            // z tile visible to all producers
            if (tile >= 2) NB_SYNC(5 + st, 384);        // wait xp tile empty

            float*       xt = sm + SM_XP   + st * (ZTILE * 192);
            const float* zt = sm + SM_ZBUF + st * (ZTILE * D_);

            for (int s = 0; s < ZTILE; s++) {
                u64 x0 = 0ull, x1 = 0ull, x2 = 0ull, x3 = 0ull;
                const ulonglong2* zr = (const ulonglong2*)(zt + s * D_);
                #pragma unroll
                for (int q = 0; q < 16; q++) {
                    ulonglong2 a0v = zr[2*q], a1v = zr[2*q+1];
                    x0 = fma2(wih[4*q+0], a0v.x, x0);
                    x1 = fma2(wih[4*q+1], a0v.y, x1);
                    x2 = fma2(wih[4*q+2], a1v.x, x2);
                    x3 = fma2(wih[4*q+3], a1v.y, x3);
                }
                xt[s*192 + j] = (sum2(x0) + sum2(x1)) + (sum2(x2) + sum2(x3)) + bih;
            }
            NB_ARRIVE(3 + st, 384);                     // publish xp tile

            if (tile + 2 < NTILES) {
                const float* src = zp + (size_t)(tile + 2) * ZTILE * D_;
                for (int i = j; i < ZTILE * D_ / 4; i += 192) {
                    unsigned dst = (unsigned)__cvta_generic_to_shared(sm + SM_ZBUF + st*(ZTILE*D_) + i*4);
                    asm volatile("cp.async.cg.shared.global [%0], [%1], 16;" :: "r"(dst), "l"(src + i*4));
                }
                asm volatile("cp.async.commit_group;");
            }
        }
    }
}

// ===========================================================================
// Kernel B: persistent MLP. 1 CTA/part, 512 threads = 4 groups x 128.
// Weights -> smem once per part; each group pipelines 16 tiles of 32 rows.
// ===========================================================================
#define ASTRIDE 132
#define SM_W1   0                         // 128*65 = 8320
#define SM_W2   (SM_W1 + 128*65)          // 64*129 = 8256
#define SM_W3   (SM_W2 + 64*129)          // 32*65  = 2080
#define SM_W4   (SM_W3 + 32*65)           // 24*33  = 792
#define SM_B1   (SM_W4 + 24*33)
#define SM_B2   (SM_B1 + 128)
#define SM_B3   (SM_B2 + 64)
#define SM_B4   (SM_B3 + 32)
#define SM_ACT  (SM_B4 + 24)              // 19696
#define ACT_PER_GRP (2 * 32 * ASTRIDE)    // 8448
#define SM_MLP_TOTAL (SM_ACT + 4*ACT_PER_GRP)   // 53488 floats = 213952 B

template<int I, int O, bool RELU>
__device__ __forceinline__
void mlp_layer128(int lt, const float* __restrict__ ain, float* __restrict__ aout,
                  const float* __restrict__ W, const float* __restrict__ bias)
{
    constexpr int OGN  = O / 4;           // 32 / 16 / 8
    constexpr int TGN  = 128 / OGN;       // 4 / 8 / 16
    constexpr int ROWS = 32 / TGN;        // 8 / 4 / 2
    constexpr int WS   = I + 1;

    const int og = lt % OGN;
    const int tg = lt / OGN;

    u64 acc[ROWS][4];
    #pragma unroll
    for (int r = 0; r < ROWS; r++)
        #pragma unroll
        for (int c = 0; c < 4; c++) acc[r][c] = 0ull;

    const float* arow = ain + tg*ROWS*ASTRIDE;

    #pragma unroll 8
    for (int k = 0; k < I; k += 2) {
        u64 av[ROWS];
        #pragma unroll
        for (int r = 0; r < ROWS; r++)
            av[r] = *(const u64*)(arow + r*ASTRIDE + k);
        #pragma unroll
        for (int c = 0; c < 4; c++) {
            const float* wrow = W + (og + c*OGN)*WS + k;
            u64 bv = pack2(wrow[0], wrow[1]);
            #pragma unroll
            for (int r = 0; r < ROWS; r++)
                acc[r][c] = fma2(av[r], bv, acc[r][c]);
        }
    }

    #pragma unroll
    for (int r = 0; r < ROWS; r++)
        #pragma unroll
        for (int c = 0; c < 4; c++) {
            int o = og + c*OGN;
            float v = sum2(acc[r][c]) + bias[o];
            if (RELU) v = fmaxf(v, 0.f);
            aout[(tg*ROWS + r)*ASTRIDE + o] = v;
        }
}

__global__ __launch_bounds__(512, 1)
void mlp_kernel(const float* __restrict__ w1, const float* __restrict__ b1,
                const float* __restrict__ w2, const float* __restrict__ b2,
                const float* __restrict__ w3, const float* __restrict__ b3,
                const float* __restrict__ w4, const float* __restrict__ b4,
                float* __restrict__ out)
{
    extern __shared__ __align__(16) float sm[];
    const int tid = threadIdx.x;
    const int p   = blockIdx.x;

    float* W1 = sm + SM_W1;  float* W2 = sm + SM_W2;
    float* W3 = sm + SM_W3;  float* W4 = sm + SM_W4;
    float* B1 = sm + SM_B1;  float* B2 = sm + SM_B2;
    float* B3 = sm + SM_B3;  float* B4 = sm + SM_B4;

    {
        const float* wp = w1 + (size_t)p*128*64;
        for (int i = tid; i < 128*64; i += 512) { int o = i >> 6, k = i & 63;  W1[o*65  + k] = wp[i]; }
        wp = w2 + (size_t)p*64*128;
        for (int i = tid; i < 64*128; i += 512) { int o = i >> 7, k = i & 127; W2[o*129 + k] = wp[i]; }
        wp = w3 + (size_t)p*32*64;
        for (int i = tid; i < 32*64;  i += 512) { int o = i >> 6, k = i & 63;  W3[o*65  + k] = wp[i]; }
        wp = w4 + (size_t)p*24*32;
        for (int i = tid; i < 24*32;  i += 512) { int o = i >> 5, k = i & 31;  W4[o*33  + k] = wp[i]; }
    }
    if (tid < 128)                 B1[tid]       = b1[p*128 + tid];
    if (tid >= 128 && tid < 192)   B2[tid - 128] = b2[p*64 + tid - 128];
    if (tid >= 192 && tid < 224)   B3[tid - 192] = b3[p*32 + tid - 192];
    if (tid >= 224 && tid < 248)   B4[tid - 224] = b4[p*24 + tid - 224];
    __syncthreads();

    const int g  = tid >> 7;        // group 0..3
    const int lt = tid & 127;
    float* AA = sm + SM_ACT + g * ACT_PER_GRP;
    float* AB = AA + 32 * ASTRIDE;

    for (int tile = g; tile < T_ / 32; tile += 4) {
        {   // 32x64 hidden rows -> AA (float4, coalesced)
            const float4* hp4 = (const float4*)(g_hs + ((size_t)p*T_ + tile*32) * H_);
            for (int i = lt; i < 32*16; i += 128) {
                int t = i >> 4, kq = i & 15;
                *(float4*)(AA + t*ASTRIDE + kq*4) = hp4[i];
            }
        }
        NB_SYNC(1 + g, 128);        // also orders prev tile's L4 reads of AB

        mlp_layer128<64, 128, true>(lt, AA, AB, W1, B1);
        NB_SYNC(1 + g, 128);
        mlp_layer128<128, 64, true>(lt, AB, AA, W2, B2);
        NB_SYNC(1 + g, 128);
        mlp_layer128<64, 32, true>(lt, AA, AB, W3, B3);
        NB_SYNC(1 + g, 128);

        float* op = out + ((size_t)p*T_ + tile*32) * OUT_;
        for (int i = lt; i < 32*OUT_; i += 128) {
            int t = i / OUT_;
            int o = i - t*OUT_;
            u64 acc = 0ull;
            const float* arow = AB + t*ASTRIDE;
            const float* wrow = W4 + o*33;
            #pragma unroll
            for (int k = 0; k < 32; k += 2)
                acc = fma2(*(const u64*)(arow + k), pack2(wrow[k], wrow[k+1]), acc);
            op[i] = sum2(acc) + B4[o];
        }
    }
}

// ---------------------------------------------------------------------------
extern "C" void kernel_launch(void* const* d_in, const int* in_sizes, int n_in,
                              void* d_out, int out_size)
{
    const float* z    = (const float*)d_in[0];
    const float* w_ih = (const float*)d_in[1];
    const float* w_hh = (const float*)d_in[2];
    const float* b_ih = (const float*)d_in[3];
    const float* b_hh = (const float*)d_in[4];
    const float* w1   = (const float*)d_in[5];
    const float* b1   = (const float*)d_in[6];
    const float* w2   = (const float*)d_in[7];
    const float* b2   = (const float*)d_in[8];
    const float* w3   = (const float*)d_in[9];
    const float* b3   = (const float*)d_in[10];
    const float* w4   = (const float*)d_in[11];
    const float* b4   = (const float*)d_in[12];
    float* out = (float*)d_out;

    const int gru_smem = SM_GRU_TOTAL * 4;   // 83456 B
    const int mlp_smem = SM_MLP_TOTAL * 4;   // 213952 B
    cudaFuncSetAttribute(gru_kernel, cudaFuncAttributeMaxDynamicSharedMemorySize, gru_smem);
    cudaFuncSetAttribute(mlp_kernel, cudaFuncAttributeMaxDynamicSharedMemorySize, mlp_smem);

    gru_kernel<<<P_, 384, gru_smem>>>(z, w_ih, b_ih, w_hh, b_hh);
    mlp_kernel<<<P_, 512, mlp_smem>>>(w1, b1, w2, b2, w3, b3, w4, b4, out);
}